// round 5
// baseline (speedup 1.0000x reference)
#include <cuda_runtime.h>
#include <cuda_fp16.h>
#include <math.h>
#include <stdint.h>

// Problem constants (fixed by dataset)
#define PDIM  100000
#define NANCH 1000
#define BPRIV 256

constexpr int CG_ITERS  = 6;
constexpr int VSPLIT    = 8;      // fp32 CG matvec splits
constexpr int GSPLIT_TC = 4;      // split-K for G
constexpr int GCHUNK    = 25024;  // multiple of 64, 4*25024 >= 100000
constexpr int CSPLIT_TC = 9;      // split-K for C
constexpr int CCHUNK    = 11136;  // multiple of 64, 9*11136 >= 100000

// ---------------- static device scratch (no allocations allowed) ----------------
__device__ __align__(256) __half g_Ah [(size_t)NANCH * PDIM];   // 200 MB
__device__ __align__(256) __half g_Al [(size_t)NANCH * PDIM];   // 200 MB
__device__ __align__(256) __half g_Ph [(size_t)BPRIV * PDIM];   // 51 MB
__device__ __align__(256) __half g_Pl [(size_t)BPRIV * PDIM];   // 51 MB
__device__ __align__(256) __half g_Yh [BPRIV * NANCH];
__device__ __align__(256) __half g_Yl [BPRIV * NANCH];
__device__ float g_Gp[GSPLIT_TC * NANCH * NANCH];       // 16 MB
__device__ float g_G [NANCH * NANCH];
__device__ float g_Cp[CSPLIT_TC * BPRIV * NANCH];       // 9.2 MB
__device__ float g_C [BPRIV * NANCH];
__device__ float g_Y [BPRIV * NANCH];
__device__ float g_Rr[BPRIV * NANCH];
__device__ float g_Pd[BPRIV * NANCH];
__device__ float g_Vp[VSPLIT * BPRIV * NANCH];
__device__ float g_rz [BPRIV];
__device__ float g_scale[BPRIV];

// ---------------- PTX helpers (plain sm_103-compatible: sm_80+ features) ----------------
__device__ __forceinline__ uint32_t smem_u32(const void* p) {
    uint32_t a;
    asm("{ .reg .u64 t; cvta.to.shared.u64 t, %1; cvt.u32.u64 %0, t; }" : "=r"(a) : "l"(p));
    return a;
}
__device__ __forceinline__ void cp_async16(uint32_t dst, const void* src, int nbytes) {
    asm volatile("cp.async.cg.shared.global [%0], [%1], 16, %2;\n"
                 :: "r"(dst), "l"(src), "r"(nbytes) : "memory");
}
__device__ __forceinline__ void cp_commit() {
    asm volatile("cp.async.commit_group;" ::: "memory");
}
__device__ __forceinline__ void ldsm_x4(uint32_t* r, uint32_t addr) {
    asm volatile("ldmatrix.sync.aligned.m8n8.x4.shared.b16 {%0,%1,%2,%3}, [%4];"
                 : "=r"(r[0]), "=r"(r[1]), "=r"(r[2]), "=r"(r[3]) : "r"(addr));
}
__device__ __forceinline__ void ldsm_x2(uint32_t* r, uint32_t addr) {
    asm volatile("ldmatrix.sync.aligned.m8n8.x2.shared.b16 {%0,%1}, [%2];"
                 : "=r"(r[0]), "=r"(r[1]) : "r"(addr));
}
__device__ __forceinline__ void ldsm_x2_trans(uint32_t* r, uint32_t addr) {
    asm volatile("ldmatrix.sync.aligned.m8n8.x2.trans.shared.b16 {%0,%1}, [%2];"
                 : "=r"(r[0]), "=r"(r[1]) : "r"(addr));
}
__device__ __forceinline__ void mma_f16(float* d, const uint32_t* a, const uint32_t* b) {
    asm volatile("mma.sync.aligned.m16n8k16.row.col.f32.f16.f16.f32 "
                 "{%0,%1,%2,%3}, {%4,%5,%6,%7}, {%8,%9}, {%0,%1,%2,%3};"
                 : "+f"(d[0]), "+f"(d[1]), "+f"(d[2]), "+f"(d[3])
                 : "r"(a[0]), "r"(a[1]), "r"(a[2]), "r"(a[3]), "r"(b[0]), "r"(b[1]));
}

// =====================================================================
// Split-fp16 MMA GEMM (fp32 accum, 3 products hh+hl+lh).
//   transB=0 (ABT): Z rows = output cols, k-contiguous (ld = ldB).
//   transB=1 (NN):  B = Zh/Zl interpreted [kTotal rows x N cols], ld = ldB;
//                   tiles stored [64 k][128 n] (256B rows), ldmatrix.trans.
//   128x128 CTA tile, k-step 64, 8 warps (64x32), 3-stage cp.async pipeline.
//   Optional fused DP epilogue: out = scale[r]*w + clamp(priv-w, +-1e-3).
// =====================================================================
constexpr int TILE_B   = 16384;             // one operand tile = 16 KB
constexpr int STAGE_B  = 4 * TILE_B;        // Xh,Xl,Zh,Zl = 64 KB
constexpr int NSTAGE   = 3;
constexpr int MMA_SMEM = NSTAGE * STAGE_B;  // 192 KB

__global__ void __launch_bounds__(256, 1)
mma_gemm(const __half* __restrict__ Xh, const __half* __restrict__ Xl,
         const __half* __restrict__ Zh, const __half* __restrict__ Zl,
         float* __restrict__ outp, int M, int N, size_t ldA, size_t ldB,
         int kTotal, int kChunk, int lowerTri, int transB,
         int epi, const float* __restrict__ priv, const float* __restrict__ scale)
{
    if (lowerTri && blockIdx.x > blockIdx.y) return;
    extern __shared__ char smem[];
    const uint32_t sb = smem_u32(smem);
    const int tid = threadIdx.x, lane = tid & 31, wid = tid >> 5;
    const int wm = wid >> 2, wn = wid & 3;           // 2x4 warp grid
    const int row0 = blockIdx.y * 128, col0 = blockIdx.x * 128;
    const int kBeg = blockIdx.z * kChunk;
    int kEnd = kBeg + kChunk; if (kEnd > kTotal) kEnd = kTotal;
    const int nIter = (kEnd - kBeg + 63) >> 6;

    const __half* bases[4] = {Xh, Xl, Zh, Zl};

    auto prefetch = [&](int s) {
        const int buf = s % NSTAGE;
        const int kb = kBeg + s * 64;
        #pragma unroll 4
        for (int i = 0; i < 16; ++i) {
            const int slot = i * 256 + tid;          // 0..4095
            const int t    = slot >> 10;             // tile 0..3
            const int w    = slot & 1023;
            int nb = 0;
            const __half* src = bases[t];
            uint32_t off;
            if (t < 2 || !transB) {
                // rows k-contiguous: [128 rows][8 x 16B chunks]
                const int row = w >> 3, ch = w & 7;
                const int rglob = ((t < 2) ? row0 : col0) + row;
                const int rmax  = (t < 2) ? M : N;
                const int kg = kb + ch * 8;
                if (rglob < rmax) {
                    int av = (kEnd - kg) * 2;
                    nb = av < 0 ? 0 : (av > 16 ? 16 : av);
                }
                if (nb > 0) src = bases[t] + (size_t)rglob * ldA * (t < 2 ? 1 : 0)
                                          + (size_t)rglob * ldB * (t < 2 ? 0 : 1) + kg;
                off = (uint32_t)(row << 7) + (uint32_t)((ch ^ (row & 7)) << 4);
            } else {
                // NN B tile: [64 k-rows][16 x 16B chunks of n]
                const int row = w >> 4, ch = w & 15;   // row = k offset, ch*8 = n offset
                const int k = kb + row;
                const int col = col0 + ch * 8;
                if (k < kEnd) {
                    int av = (N - col) * 2;
                    nb = av < 0 ? 0 : (av > 16 ? 16 : av);
                }
                if (nb > 0) src = bases[t] + (size_t)k * ldB + col;
                off = (uint32_t)(row << 8) + (uint32_t)((ch ^ (row & 7)) << 4);
            }
            cp_async16(sb + (uint32_t)(buf * 4 + t) * TILE_B + off, src, nb);
        }
        cp_commit();
    };

    float acc[4][4][4];
    #pragma unroll
    for (int mt = 0; mt < 4; ++mt)
        #pragma unroll
        for (int nt = 0; nt < 4; ++nt)
            #pragma unroll
            for (int e = 0; e < 4; ++e) acc[mt][nt][e] = 0.f;

    prefetch(0);
    if (nIter > 1) prefetch(1);

    const int arow  = wm * 64 + (lane & 15);
    const int ahalf = lane >> 4;
    const int brow  = wn * 32 + (lane & 7);
    const int bhalf = (lane >> 3) & 1;

    for (int it = 0; it < nIter; ++it) {
        if (it + 1 < nIter) asm volatile("cp.async.wait_group 1;" ::: "memory");
        else                asm volatile("cp.async.wait_group 0;" ::: "memory");
        __syncthreads();
        if (it + 2 < nIter) prefetch(it + 2);

        const uint32_t tb  = sb + (uint32_t)(it % NSTAGE) * STAGE_B;
        const uint32_t tXh = tb, tXl = tb + TILE_B;
        const uint32_t tZh = tb + 2 * TILE_B, tZl = tb + 3 * TILE_B;

        #pragma unroll
        for (int ks = 0; ks < 4; ++ks) {
            uint32_t ah[4][4], al[4][4];
            #pragma unroll
            for (int mt = 0; mt < 4; ++mt) {
                const int r  = arow + mt * 16;
                const int ch = (ks * 2 + ahalf) ^ (r & 7);
                const uint32_t off = (uint32_t)(r << 7) + (uint32_t)(ch << 4);
                ldsm_x4(ah[mt], tXh + off);
                ldsm_x4(al[mt], tXl + off);
            }
            uint32_t bh[4][2], bl[4][2];
            if (!transB) {
                #pragma unroll
                for (int nt = 0; nt < 4; ++nt) {
                    const int r  = brow + nt * 8;
                    const int ch = (ks * 2 + bhalf) ^ (r & 7);
                    const uint32_t off = (uint32_t)(r << 7) + (uint32_t)(ch << 4);
                    ldsm_x2(bh[nt], tZh + off);
                    ldsm_x2(bl[nt], tZl + off);
                }
            } else {
                const int r = ks * 16 + (lane & 15);
                #pragma unroll
                for (int nt = 0; nt < 4; ++nt) {
                    const int cn = wn * 4 + nt;
                    const uint32_t off = (uint32_t)(r << 8)
                                       + (uint32_t)((cn ^ (r & 7)) << 4);
                    ldsm_x2_trans(bh[nt], tZh + off);
                    ldsm_x2_trans(bl[nt], tZl + off);
                }
            }
            #pragma unroll
            for (int mt = 0; mt < 4; ++mt)
                #pragma unroll
                for (int nt = 0; nt < 4; ++nt) {
                    mma_f16(acc[mt][nt], ah[mt], bh[nt]);
                    mma_f16(acc[mt][nt], ah[mt], bl[nt]);
                    mma_f16(acc[mt][nt], al[mt], bh[nt]);
                }
        }
        __syncthreads();
    }

    float* dst = outp + (size_t)blockIdx.z * (size_t)M * N;
    #pragma unroll
    for (int mt = 0; mt < 4; ++mt) {
        const int rA = row0 + wm * 64 + mt * 16 + (lane >> 2);
        #pragma unroll
        for (int nt = 0; nt < 4; ++nt) {
            const int c = col0 + wn * 32 + nt * 8 + (lane & 3) * 2;
            #pragma unroll
            for (int h = 0; h < 2; ++h) {
                const int r = rA + h * 8;
                if (r >= M || c + 1 >= N) continue;
                const float v0 = acc[mt][nt][2 * h + 0];
                const float v1 = acc[mt][nt][2 * h + 1];
                float* po = dst + (size_t)r * N + c;
                if (epi) {
                    const float sc = scale[r];
                    const float* pp = priv + (size_t)r * N + c;
                    float r0 = pp[0] - v0; r0 = fminf(fmaxf(r0, -1e-3f), 1e-3f);
                    float r1 = pp[1] - v1; r1 = fminf(fmaxf(r1, -1e-3f), 1e-3f);
                    *(float2*)po = make_float2(sc * v0 + r0, sc * v1 + r1);
                } else {
                    *(float2*)po = make_float2(v0, v1);
                }
            }
        }
    }
}

// ---------------- converts (pure streaming hi/lo split) ----------------
__global__ void convSplit(const float* __restrict__ X,
                          __half* __restrict__ H, __half* __restrict__ L, size_t n)
{
    const size_t stride = (size_t)gridDim.x * blockDim.x * 4;
    for (size_t i = ((size_t)blockIdx.x * blockDim.x + threadIdx.x) * 4; i < n; i += stride) {
        if (i + 4 <= n) {
            const float4 v = *(const float4*)(X + i);
            __half h0 = __float2half(v.x), h1 = __float2half(v.y);
            __half h2 = __float2half(v.z), h3 = __float2half(v.w);
            __half2 hh0 = __halves2half2(h0, h1), hh1 = __halves2half2(h2, h3);
            __half2 ll0 = __halves2half2(__float2half(v.x - __half2float(h0)),
                                         __float2half(v.y - __half2float(h1)));
            __half2 ll1 = __halves2half2(__float2half(v.z - __half2float(h2)),
                                         __float2half(v.w - __half2float(h3)));
            *(__half2*)(H + i)     = hh0;
            *(__half2*)(H + i + 2) = hh1;
            *(__half2*)(L + i)     = ll0;
            *(__half2*)(L + i + 2) = ll1;
        } else {
            for (size_t e = i; e < n; ++e) {
                const float v = X[e];
                const __half hb = __float2half(v);
                H[e] = hb;
                L[e] = __float2half(v - __half2float(hb));
            }
        }
    }
}

// ---------------- G reduce + mirror (lower-tri partials) ----------------
__global__ void reduceG(const float* __restrict__ Gp, float* __restrict__ G)
{
    const int idx = blockIdx.x * 256 + threadIdx.x;
    if (idx >= NANCH * NANCH) return;
    const int i = idx / NANCH, j = idx - i * NANCH;
    const int s0 = (j > i) ? (j * NANCH + i) : idx;
    float s = 0.f;
    #pragma unroll
    for (int z = 0; z < GSPLIT_TC; ++z) s += Gp[(size_t)z * NANCH * NANCH + s0];
    G[idx] = s;
}

// =====================================================================
// fp32 SIMT split-K GEMM (CG matvec only: 256x1000 @ G 1000x1000)
// =====================================================================
__global__ void __launch_bounds__(256, 2)
gemm_abt_splitk(const float* __restrict__ X, const float* __restrict__ Z,
                float* __restrict__ partial,
                int M, int N, int ldx, int ldz, int kTotal, int kChunk)
{
    __shared__ __align__(16) float Xs[2][16][132];
    __shared__ __align__(16) float Zs[2][16][132];

    const int tid = threadIdx.x;
    const int bj = blockIdx.x, bi = blockIdx.y, zs = blockIdx.z;
    const int row0 = bi * 128, col0 = bj * 128;
    const int kBeg = zs * kChunk;
    int kEnd = kBeg + kChunk; if (kEnd > kTotal) kEnd = kTotal;
    const int nIter = (kEnd - kBeg + 15) >> 4;

    const int rbase = tid >> 2;
    const int c0    = (tid & 3) << 2;
    const int tx = tid & 15, ty = tid >> 4;

    float4 sx[2], sz[2];

    auto loadStage = [&](int it) {
        const int kb = kBeg + it * 16;
        const int k  = kb + c0;
        #pragma unroll
        for (int q = 0; q < 2; ++q) {
            const int rr = rbase + q * 64;
            float4 v = make_float4(0.f, 0.f, 0.f, 0.f);
            const int row = row0 + rr;
            if (row < M) {
                const float* p = X + (size_t)row * ldx + k;
                if (k + 4 <= kEnd) v = *(const float4*)p;
                else { float* pv = (float*)&v; for (int e = 0; e < 4; ++e) if (k + e < kEnd) pv[e] = p[e]; }
            }
            sx[q] = v;
            float4 w = make_float4(0.f, 0.f, 0.f, 0.f);
            const int colr = col0 + rr;
            if (colr < N) {
                const float* p = Z + (size_t)colr * ldz + k;
                if (k + 4 <= kEnd) w = *(const float4*)p;
                else { float* pw = (float*)&w; for (int e = 0; e < 4; ++e) if (k + e < kEnd) pw[e] = p[e]; }
            }
            sz[q] = w;
        }
    };
    auto storeStage = [&](int buf) {
        #pragma unroll
        for (int q = 0; q < 2; ++q) {
            const int rr = rbase + q * 64;
            Xs[buf][c0+0][rr] = sx[q].x; Xs[buf][c0+1][rr] = sx[q].y;
            Xs[buf][c0+2][rr] = sx[q].z; Xs[buf][c0+3][rr] = sx[q].w;
            Zs[buf][c0+0][rr] = sz[q].x; Zs[buf][c0+1][rr] = sz[q].y;
            Zs[buf][c0+2][rr] = sz[q].z; Zs[buf][c0+3][rr] = sz[q].w;
        }
    };

    float acc[8][8];
    #pragma unroll
    for (int i = 0; i < 8; ++i)
        #pragma unroll
        for (int j = 0; j < 8; ++j) acc[i][j] = 0.f;

    loadStage(0); storeStage(0); __syncthreads();

    for (int it = 0; it < nIter; ++it) {
        const int buf = it & 1;
        if (it + 1 < nIter) loadStage(it + 1);
        #pragma unroll
        for (int k = 0; k < 16; ++k) {
            float xf[8], zf[8];
            *(float4*)(xf)     = *(const float4*)&Xs[buf][k][ty*8];
            *(float4*)(xf + 4) = *(const float4*)&Xs[buf][k][ty*8 + 4];
            *(float4*)(zf)     = *(const float4*)&Zs[buf][k][tx*8];
            *(float4*)(zf + 4) = *(const float4*)&Zs[buf][k][tx*8 + 4];
            #pragma unroll
            for (int i = 0; i < 8; ++i)
                #pragma unroll
                for (int j = 0; j < 8; ++j)
                    acc[i][j] += xf[i] * zf[j];
        }
        if (it + 1 < nIter) storeStage(buf ^ 1);
        __syncthreads();
    }

    float* dst = partial + (size_t)zs * M * N;
    #pragma unroll
    for (int i = 0; i < 8; ++i) {
        const int row = row0 + ty * 8 + i;
        if (row >= M) continue;
        #pragma unroll
        for (int j = 0; j < 8; ++j) {
            const int col = col0 + tx * 8 + j;
            if (col < N) dst[(size_t)row * N + col] = acc[i][j];
        }
    }
}

// ---------------- fused CG kernels (one block per RHS row) ----------------
__device__ __forceinline__ float blockReduce256(float v, float* sm)
{
    const int t = threadIdx.x;
    __syncthreads();
    sm[t] = v; __syncthreads();
    #pragma unroll
    for (int s = 128; s > 0; s >>= 1) {
        if (t < s) sm[t] += sm[t + s];
        __syncthreads();
    }
    return sm[0];
}

// init: reduce Cp partials -> C, set Y=0, Rr=Pd=C, rz=|C|^2
__global__ void cg_init(const float* __restrict__ Cp, float* __restrict__ C,
                        float* __restrict__ Y, float* __restrict__ Rr,
                        float* __restrict__ Pd, float* __restrict__ rz)
{
    __shared__ float sm[256];
    const int b = blockIdx.x, t = threadIdx.x;
    float s = 0.f;
    #pragma unroll
    for (int i = 0; i < 4; ++i) {
        const int j = t + i * 256;
        if (j < NANCH) {
            float c = 0.f;
            #pragma unroll
            for (int z = 0; z < CSPLIT_TC; ++z)
                c += Cp[(size_t)z * BPRIV * NANCH + b * NANCH + j];
            C[b * NANCH + j]  = c;
            Y[b * NANCH + j]  = 0.f;
            Rr[b * NANCH + j] = c;
            Pd[b * NANCH + j] = c;
            s += c * c;
        }
    }
    const float tot = blockReduce256(s, sm);
    if (t == 0) rz[b] = tot;
}

// one full CG step per block: reduce Vp, pv-dot, alpha, update Y/Rr, rz2, beta, next Pd
__global__ void cg_step(const float* __restrict__ Vp, float* __restrict__ Pd,
                        float* __restrict__ Y, float* __restrict__ Rr,
                        float* __restrict__ rz)
{
    __shared__ float sm[256];
    const int b = blockIdx.x, t = threadIdx.x;
    float v[4], p[4], rn[4];
    float dot = 0.f;
    #pragma unroll
    for (int i = 0; i < 4; ++i) {
        const int j = t + i * 256;
        float vv = 0.f, pp = 0.f;
        if (j < NANCH) {
            #pragma unroll
            for (int z = 0; z < VSPLIT; ++z)
                vv += Vp[(size_t)z * BPRIV * NANCH + b * NANCH + j];
            pp = Pd[b * NANCH + j];
        }
        v[i] = vv; p[i] = pp;
        dot += pp * vv;
    }
    const float pv = blockReduce256(dot, sm);
    const float rzb = rz[b];
    const float alpha = (pv > 0.f) ? rzb / pv : 0.f;

    float rs = 0.f;
    #pragma unroll
    for (int i = 0; i < 4; ++i) {
        const int j = t + i * 256;
        if (j < NANCH) {
            const float r = Rr[b * NANCH + j] - alpha * v[i];
            rn[i] = r;
            Y[b * NANCH + j] += alpha * p[i];
            rs += r * r;
        } else rn[i] = 0.f;
    }
    const float rz2 = blockReduce256(rs, sm);
    const float beta = (rzb > 0.f) ? rz2 / rzb : 0.f;
    #pragma unroll
    for (int i = 0; i < 4; ++i) {
        const int j = t + i * 256;
        if (j < NANCH) {
            Rr[b * NANCH + j] = rn[i];
            Pd[b * NANCH + j] = rn[i] + beta * p[i];
        }
    }
    if (t == 0) rz[b] = rz2;
}

// scale_b = min(1/||emb_b||, 1),  ||emb_b||^2 = <Y_b, C_b>
__global__ void scale_kernel(const float* __restrict__ Y, const float* __restrict__ C,
                             float* __restrict__ scale)
{
    __shared__ float sm[256];
    const int b = blockIdx.x;
    float s = 0.f;
    for (int j = threadIdx.x; j < NANCH; j += 256)
        s += Y[b * NANCH + j] * C[b * NANCH + j];
    const float tot = blockReduce256(s, sm);
    if (threadIdx.x == 0) {
        const float nrm = sqrtf(fmaxf(tot, 0.f));
        scale[b] = (nrm > 1.0f) ? 1.0f / nrm : 1.0f;
    }
}

// =====================================================================
extern "C" void kernel_launch(void* const* d_in, const int* in_sizes, int n_in,
                              void* d_out, int out_size)
{
    const float* A    = (const float*)d_in[0];   // pub_grad [1000, 100000]
    const float* priv = (const float*)d_in[1];   // priv_grad [256, 100000]
    float* out = (float*)d_out;                  // [256, 100000]

    __half *Ah, *Al, *Ph, *Pl, *Yh, *Yl;
    float *Gp, *G, *Cp, *C, *Y, *Rr, *Pd, *Vp, *rz, *sc;
    cudaGetSymbolAddress((void**)&Ah, g_Ah);
    cudaGetSymbolAddress((void**)&Al, g_Al);
    cudaGetSymbolAddress((void**)&Ph, g_Ph);
    cudaGetSymbolAddress((void**)&Pl, g_Pl);
    cudaGetSymbolAddress((void**)&Yh, g_Yh);
    cudaGetSymbolAddress((void**)&Yl, g_Yl);
    cudaGetSymbolAddress((void**)&Gp, g_Gp);
    cudaGetSymbolAddress((void**)&G,  g_G);
    cudaGetSymbolAddress((void**)&Cp, g_Cp);
    cudaGetSymbolAddress((void**)&C,  g_C);
    cudaGetSymbolAddress((void**)&Y,  g_Y);
    cudaGetSymbolAddress((void**)&Rr, g_Rr);
    cudaGetSymbolAddress((void**)&Pd, g_Pd);
    cudaGetSymbolAddress((void**)&Vp, g_Vp);
    cudaGetSymbolAddress((void**)&rz, g_rz);
    cudaGetSymbolAddress((void**)&sc, g_scale);

    cudaFuncSetAttribute(mma_gemm, cudaFuncAttributeMaxDynamicSharedMemorySize, MMA_SMEM);

    // 1) hi/lo fp16 splits (pure streaming; no transposed copies needed)
    convSplit<<<2048, 256>>>(A,    Ah, Al, (size_t)NANCH * PDIM);
    convSplit<<<512,  256>>>(priv, Ph, Pl, (size_t)BPRIV * PDIM);

    // 2) G = A A^T  (lower triangle + fused mirror in reduce)
    mma_gemm<<<dim3(8, 8, GSPLIT_TC), 256, MMA_SMEM>>>(
        Ah, Al, Ah, Al, Gp, NANCH, NANCH, (size_t)PDIM, (size_t)PDIM,
        PDIM, GCHUNK, 1, 0, 0, nullptr, nullptr);
    reduceG<<<(NANCH * NANCH + 255) / 256, 256>>>(Gp, G);

    // 3) C = priv A^T
    mma_gemm<<<dim3(8, 2, CSPLIT_TC), 256, MMA_SMEM>>>(
        Ph, Pl, Ah, Al, Cp, BPRIV, NANCH, (size_t)PDIM, (size_t)PDIM,
        PDIM, CCHUNK, 0, 0, 0, nullptr, nullptr);

    // 4) batched CG: G Y^T = C^T (256 RHS) — init fuses the C-partials reduce
    cg_init<<<BPRIV, 256>>>(Cp, C, Y, Rr, Pd, rz);
    for (int it = 0; it < CG_ITERS; ++it) {
        gemm_abt_splitk<<<dim3(8, 2, VSPLIT), 256>>>(Pd, G, Vp, BPRIV, NANCH,
                                                     NANCH, NANCH, NANCH, 128);
        cg_step<<<BPRIV, 256>>>(Vp, Pd, Y, Rr, rz);
    }

    // 5) clip scale + split Y
    scale_kernel<<<BPRIV, 256>>>(Y, C, sc);
    convSplit<<<64, 256>>>(Y, Yh, Yl, (size_t)BPRIV * NANCH);

    // 6) W = Y * A with fused DP epilogue, direct to out (NN path: B = A rows k-major)
    mma_gemm<<<dim3((PDIM + 127) / 128, 2, 1), 256, MMA_SMEM>>>(
        Yh, Yl, Ah, Al, out, BPRIV, PDIM, (size_t)NANCH, (size_t)PDIM,
        NANCH, NANCH, 0, 1, 1, priv, sc);
}

// round 6
// speedup vs baseline: 1.1994x; 1.1994x over previous
#include <cuda_runtime.h>
#include <cuda_bf16.h>
#include <math.h>
#include <stdint.h>

// Problem constants (fixed by dataset)
#define PDIM  100000
#define NANCH 1000
#define BPRIV 256

constexpr int CG_ITERS  = 6;
constexpr int VSPLIT    = 8;      // fp32 CG matvec splits
constexpr int GSPLIT_TC = 4;      // split-K for G
constexpr int GCHUNK    = 25024;  // multiple of 64, 4*25024 >= 100000
constexpr int CSPLIT_TC = 9;      // split-K for C
constexpr int CCHUNK    = 11136;  // multiple of 64, 9*11136 >= 100000

// ---------------- static device scratch (no allocations allowed) ----------------
__device__ __align__(256) __nv_bfloat16 g_Ah [(size_t)NANCH * PDIM];   // 200 MB
__device__ __align__(256) __nv_bfloat16 g_Al [(size_t)NANCH * PDIM];   // 200 MB
__device__ __align__(256) __nv_bfloat16 g_Ath[(size_t)PDIM * NANCH];   // 200 MB
__device__ __align__(256) __nv_bfloat16 g_Atl[(size_t)PDIM * NANCH];   // 200 MB
__device__ __align__(256) __nv_bfloat16 g_Ph [(size_t)BPRIV * PDIM];   // 51 MB
__device__ __align__(256) __nv_bfloat16 g_Pl [(size_t)BPRIV * PDIM];   // 51 MB
__device__ __align__(256) __nv_bfloat16 g_Yh [BPRIV * NANCH];
__device__ __align__(256) __nv_bfloat16 g_Yl [BPRIV * NANCH];
__device__ float g_Gp[GSPLIT_TC * NANCH * NANCH];       // 16 MB
__device__ float g_G [NANCH * NANCH];
__device__ float g_Cp[CSPLIT_TC * BPRIV * NANCH];       // 9.2 MB
__device__ float g_C [BPRIV * NANCH];
__device__ float g_Y [BPRIV * NANCH];
__device__ float g_Rr[BPRIV * NANCH];
__device__ float g_Pd[BPRIV * NANCH];
__device__ float g_Vp[VSPLIT * BPRIV * NANCH];
__device__ float g_rz [BPRIV];
__device__ float g_scale[BPRIV];

// ---------------- PTX helpers (plain sm_103-compatible: sm_80+ features) ----------------
__device__ __forceinline__ uint32_t smem_u32(const void* p) {
    uint32_t a;
    asm("{ .reg .u64 t; cvta.to.shared.u64 t, %1; cvt.u32.u64 %0, t; }" : "=r"(a) : "l"(p));
    return a;
}
__device__ __forceinline__ void cp_async16(uint32_t dst, const void* src, int nbytes) {
    asm volatile("cp.async.cg.shared.global [%0], [%1], 16, %2;\n"
                 :: "r"(dst), "l"(src), "r"(nbytes) : "memory");
}
__device__ __forceinline__ void cp_commit() {
    asm volatile("cp.async.commit_group;" ::: "memory");
}
__device__ __forceinline__ void ldsm_x4(uint32_t* r, uint32_t addr) {
    asm volatile("ldmatrix.sync.aligned.m8n8.x4.shared.b16 {%0,%1,%2,%3}, [%4];"
                 : "=r"(r[0]), "=r"(r[1]), "=r"(r[2]), "=r"(r[3]) : "r"(addr));
}
__device__ __forceinline__ void ldsm_x2(uint32_t* r, uint32_t addr) {
    asm volatile("ldmatrix.sync.aligned.m8n8.x2.shared.b16 {%0,%1}, [%2];"
                 : "=r"(r[0]), "=r"(r[1]) : "r"(addr));
}
__device__ __forceinline__ void mma_bf16(float* d, const uint32_t* a, const uint32_t* b) {
    asm volatile("mma.sync.aligned.m16n8k16.row.col.f32.bf16.bf16.f32 "
                 "{%0,%1,%2,%3}, {%4,%5,%6,%7}, {%8,%9}, {%0,%1,%2,%3};"
                 : "+f"(d[0]), "+f"(d[1]), "+f"(d[2]), "+f"(d[3])
                 : "r"(a[0]), "r"(a[1]), "r"(a[2]), "r"(a[3]), "r"(b[0]), "r"(b[1]));
}

// =====================================================================
// Split-bf16 MMA GEMM (identical to R4 known-good):  partial[z] = X * Z^T
//   128x128 CTA tile, k-step 64, 8 warps (64x32 warp tiles, m16n8k16),
//   swizzled smem, 3-stage cp.async pipeline, 3 products hh+hl+lh.
//   Optional fused DP epilogue: out = scale[r]*w + clamp(priv-w, +-1e-3).
// =====================================================================
constexpr int TILE_B  = 128 * 128;         // one 128x64 bf16 tile = 16 KB
constexpr int STAGE_B = 4 * TILE_B;        // Xh,Xl,Zh,Zl = 64 KB
constexpr int NSTAGE  = 3;
constexpr int MMA_SMEM = NSTAGE * STAGE_B; // 192 KB

__global__ void __launch_bounds__(256, 1)
mma_gemm_abt(const __nv_bfloat16* __restrict__ Xh, const __nv_bfloat16* __restrict__ Xl,
             const __nv_bfloat16* __restrict__ Zh, const __nv_bfloat16* __restrict__ Zl,
             float* __restrict__ outp, int M, int N, size_t ldK,
             int kTotal, int kChunk, int lowerTri,
             int epi, const float* __restrict__ priv, const float* __restrict__ scale)
{
    if (lowerTri && blockIdx.x > blockIdx.y) return;
    extern __shared__ char smem[];
    const uint32_t sb = smem_u32(smem);
    const int tid = threadIdx.x, lane = tid & 31, wid = tid >> 5;
    const int wm = wid >> 2, wn = wid & 3;           // 2x4 warp grid
    const int row0 = blockIdx.y * 128, col0 = blockIdx.x * 128;
    const int kBeg = blockIdx.z * kChunk;
    int kEnd = kBeg + kChunk; if (kEnd > kTotal) kEnd = kTotal;
    const int nIter = (kEnd - kBeg + 63) >> 6;

    const __nv_bfloat16* bases[4] = {Xh, Xl, Zh, Zl};

    auto prefetch = [&](int s) {
        const int buf = s % NSTAGE;
        const int kb = kBeg + s * 64;
        #pragma unroll 4
        for (int i = 0; i < 16; ++i) {
            const int slot = i * 256 + tid;          // 0..4095
            const int t    = slot >> 10;             // tile 0..3
            const int w    = slot & 1023;
            const int row  = w >> 3;                 // 0..127
            const int ch   = w & 7;                  // 16B chunk
            const int rglob = ((t < 2) ? row0 : col0) + row;
            const int rmax  = (t < 2) ? M : N;
            const int kg = kb + ch * 8;
            int nb = 0;
            if (rglob < rmax) {
                int av = (kEnd - kg) * 2;
                nb = av < 0 ? 0 : (av > 16 ? 16 : av);
            }
            const __nv_bfloat16* src = (nb > 0) ? bases[t] + (size_t)rglob * ldK + kg
                                                : bases[t];
            const uint32_t dst = sb + (uint32_t)(buf * 4 + t) * (TILE_B)
                               + (uint32_t)(row << 7) + (uint32_t)((ch ^ (row & 7)) << 4);
            cp_async16(dst, src, nb);
        }
        cp_commit();
    };

    float acc[4][4][4];
    #pragma unroll
    for (int mt = 0; mt < 4; ++mt)
        #pragma unroll
        for (int nt = 0; nt < 4; ++nt)
            #pragma unroll
            for (int e = 0; e < 4; ++e) acc[mt][nt][e] = 0.f;

    prefetch(0);
    if (nIter > 1) prefetch(1);

    const int arow  = wm * 64 + (lane & 15);
    const int ahalf = lane >> 4;                    // k-half (0/1) within k16
    const int brow  = wn * 32 + (lane & 7);
    const int bhalf = (lane >> 3) & 1;

    for (int it = 0; it < nIter; ++it) {
        if (it + 1 < nIter) asm volatile("cp.async.wait_group 1;" ::: "memory");
        else                asm volatile("cp.async.wait_group 0;" ::: "memory");
        __syncthreads();
        if (it + 2 < nIter) prefetch(it + 2);

        const uint32_t tb  = sb + (uint32_t)(it % NSTAGE) * STAGE_B;
        const uint32_t tXh = tb, tXl = tb + TILE_B;
        const uint32_t tZh = tb + 2 * TILE_B, tZl = tb + 3 * TILE_B;

        #pragma unroll
        for (int ks = 0; ks < 4; ++ks) {
            uint32_t ah[4][4], al[4][4];
            #pragma unroll
            for (int mt = 0; mt < 4; ++mt) {
                const int r  = arow + mt * 16;
                const int ch = (ks * 2 + ahalf) ^ (r & 7);
                const uint32_t off = (uint32_t)(r << 7) + (uint32_t)(ch << 4);
                ldsm_x4(ah[mt], tXh + off);
                ldsm_x4(al[mt], tXl + off);
            }
            uint32_t bh[4][2], bl[4][2];
            #pragma unroll
            for (int nt = 0; nt < 4; ++nt) {
                const int r  = brow + nt * 8;
                const int ch = (ks * 2 + bhalf) ^ (r & 7);
                const uint32_t off = (uint32_t)(r << 7) + (uint32_t)(ch << 4);
                ldsm_x2(bh[nt], tZh + off);
                ldsm_x2(bl[nt], tZl + off);
            }
            #pragma unroll
            for (int mt = 0; mt < 4; ++mt)
                #pragma unroll
                for (int nt = 0; nt < 4; ++nt) {
                    mma_bf16(acc[mt][nt], ah[mt], bh[nt]);
                    mma_bf16(acc[mt][nt], ah[mt], bl[nt]);
                    mma_bf16(acc[mt][nt], al[mt], bh[nt]);
                }
        }
        __syncthreads();
    }

    // store: d0,d1 -> (r, c..c+1); d2,d3 -> (r+8, c..c+1)
    float* dst = outp + (size_t)blockIdx.z * (size_t)M * N;
    #pragma unroll
    for (int mt = 0; mt < 4; ++mt) {
        const int rA = row0 + wm * 64 + mt * 16 + (lane >> 2);
        #pragma unroll
        for (int nt = 0; nt < 4; ++nt) {
            const int c = col0 + wn * 32 + nt * 8 + (lane & 3) * 2;
            #pragma unroll
            for (int h = 0; h < 2; ++h) {
                const int r = rA + h * 8;
                if (r >= M || c >= N) continue;
                const float v0 = acc[mt][nt][2 * h + 0];
                const float v1 = acc[mt][nt][2 * h + 1];
                float* po = dst + (size_t)r * N + c;
                if (epi) {
                    const float sc = scale[r];
                    const float* pp = priv + (size_t)r * N + c;
                    float r0 = pp[0] - v0; r0 = fminf(fmaxf(r0, -1e-3f), 1e-3f);
                    float r1 = pp[1] - v1; r1 = fminf(fmaxf(r1, -1e-3f), 1e-3f);
                    *(float2*)po = make_float2(sc * v0 + r0, sc * v1 + r1);
                } else {
                    *(float2*)po = make_float2(v0, v1);
                }
            }
        }
    }
}

// ---------------- converts ----------------
__global__ void convA(const float* __restrict__ A,
                      __nv_bfloat16* __restrict__ Ah, __nv_bfloat16* __restrict__ Al,
                      __nv_bfloat16* __restrict__ Ath, __nv_bfloat16* __restrict__ Atl)
{
    __shared__ __nv_bfloat16 sh[32][33];
    __shared__ __nv_bfloat16 sl[32][33];
    const int tx = threadIdx.x, ty = threadIdx.y;
    const int col = blockIdx.x * 32 + tx;      // p
    #pragma unroll
    for (int k = 0; k < 4; ++k) {
        const int row = blockIdx.y * 32 + ty + k * 8;   // n
        float v = 0.f;
        if (row < NANCH) v = A[(size_t)row * PDIM + col];
        const __nv_bfloat16 hb = __float2bfloat16(v);
        const __nv_bfloat16 lb = __float2bfloat16(v - __bfloat162float(hb));
        if (row < NANCH) {
            Ah[(size_t)row * PDIM + col] = hb;
            Al[(size_t)row * PDIM + col] = lb;
        }
        sh[ty + k * 8][tx] = hb;
        sl[ty + k * 8][tx] = lb;
    }
    __syncthreads();
    #pragma unroll
    for (int k = 0; k < 4; ++k) {
        const int p = blockIdx.x * 32 + ty + k * 8;
        const int n = blockIdx.y * 32 + tx;
        if (n < NANCH) {
            Ath[(size_t)p * NANCH + n] = sh[tx][ty + k * 8];
            Atl[(size_t)p * NANCH + n] = sl[tx][ty + k * 8];
        }
    }
}

__global__ void convSplit(const float* __restrict__ X,
                          __nv_bfloat16* __restrict__ H, __nv_bfloat16* __restrict__ L,
                          size_t n)
{
    const size_t i = ((size_t)blockIdx.x * blockDim.x + threadIdx.x) * 2;
    const size_t stride = (size_t)gridDim.x * blockDim.x * 2;
    for (size_t j = i; j < n; j += stride) {
        if (j + 2 <= n) {
            const float2 v = *(const float2*)(X + j);
            const __nv_bfloat16 h0 = __float2bfloat16(v.x);
            const __nv_bfloat16 h1 = __float2bfloat16(v.y);
            __nv_bfloat162 hh; hh.x = h0; hh.y = h1;
            __nv_bfloat162 ll;
            ll.x = __float2bfloat16(v.x - __bfloat162float(h0));
            ll.y = __float2bfloat16(v.y - __bfloat162float(h1));
            *(__nv_bfloat162*)(H + j) = hh;
            *(__nv_bfloat162*)(L + j) = ll;
        } else {
            const float v = X[j];
            const __nv_bfloat16 hb = __float2bfloat16(v);
            H[j] = hb;
            L[j] = __float2bfloat16(v - __bfloat162float(hb));
        }
    }
}

// ---------------- G reduce + mirror (lower-tri partials, fused) ----------------
__global__ void reduceG(const float* __restrict__ Gp, float* __restrict__ G)
{
    const int idx = blockIdx.x * 256 + threadIdx.x;
    if (idx >= NANCH * NANCH) return;
    const int i = idx / NANCH, j = idx - i * NANCH;
    const int s0 = (j > i) ? (j * NANCH + i) : idx;
    float s = 0.f;
    #pragma unroll
    for (int z = 0; z < GSPLIT_TC; ++z) s += Gp[(size_t)z * NANCH * NANCH + s0];
    G[idx] = s;
}

// =====================================================================
// fp32 SIMT split-K GEMM (CG matvec only: Pd[256x1000] @ G[1000x1000])
// =====================================================================
__global__ void __launch_bounds__(256, 2)
gemm_abt_splitk(const float* __restrict__ X, const float* __restrict__ Z,
                float* __restrict__ partial,
                int M, int N, int ldx, int ldz, int kTotal, int kChunk)
{
    __shared__ __align__(16) float Xs[2][16][132];
    __shared__ __align__(16) float Zs[2][16][132];

    const int tid = threadIdx.x;
    const int bj = blockIdx.x, bi = blockIdx.y, zs = blockIdx.z;
    const int row0 = bi * 128, col0 = bj * 128;
    const int kBeg = zs * kChunk;
    int kEnd = kBeg + kChunk; if (kEnd > kTotal) kEnd = kTotal;
    const int nIter = (kEnd - kBeg + 15) >> 4;

    const int rbase = tid >> 2;
    const int c0    = (tid & 3) << 2;
    const int tx = tid & 15, ty = tid >> 4;

    float4 sx[2], sz[2];

    auto loadStage = [&](int it) {
        const int kb = kBeg + it * 16;
        const int k  = kb + c0;
        #pragma unroll
        for (int q = 0; q < 2; ++q) {
            const int rr = rbase + q * 64;
            float4 v = make_float4(0.f, 0.f, 0.f, 0.f);
            const int row = row0 + rr;
            if (row < M) {
                const float* p = X + (size_t)row * ldx + k;
                if (k + 4 <= kEnd) v = *(const float4*)p;
                else { float* pv = (float*)&v; for (int e = 0; e < 4; ++e) if (k + e < kEnd) pv[e] = p[e]; }
            }
            sx[q] = v;
            float4 w = make_float4(0.f, 0.f, 0.f, 0.f);
            const int colr = col0 + rr;
            if (colr < N) {
                const float* p = Z + (size_t)colr * ldz + k;
                if (k + 4 <= kEnd) w = *(const float4*)p;
                else { float* pw = (float*)&w; for (int e = 0; e < 4; ++e) if (k + e < kEnd) pw[e] = p[e]; }
            }
            sz[q] = w;
        }
    };
    auto storeStage = [&](int buf) {
        #pragma unroll
        for (int q = 0; q < 2; ++q) {
            const int rr = rbase + q * 64;
            Xs[buf][c0+0][rr] = sx[q].x; Xs[buf][c0+1][rr] = sx[q].y;
            Xs[buf][c0+2][rr] = sx[q].z; Xs[buf][c0+3][rr] = sx[q].w;
            Zs[buf][c0+0][rr] = sz[q].x; Zs[buf][c0+1][rr] = sz[q].y;
            Zs[buf][c0+2][rr] = sz[q].z; Zs[buf][c0+3][rr] = sz[q].w;
        }
    };

    float acc[8][8];
    #pragma unroll
    for (int i = 0; i < 8; ++i)
        #pragma unroll
        for (int j = 0; j < 8; ++j) acc[i][j] = 0.f;

    loadStage(0); storeStage(0); __syncthreads();

    for (int it = 0; it < nIter; ++it) {
        const int buf = it & 1;
        if (it + 1 < nIter) loadStage(it + 1);
        #pragma unroll
        for (int k = 0; k < 16; ++k) {
            float xf[8], zf[8];
            *(float4*)(xf)     = *(const float4*)&Xs[buf][k][ty*8];
            *(float4*)(xf + 4) = *(const float4*)&Xs[buf][k][ty*8 + 4];
            *(float4*)(zf)     = *(const float4*)&Zs[buf][k][tx*8];
            *(float4*)(zf + 4) = *(const float4*)&Zs[buf][k][tx*8 + 4];
            #pragma unroll
            for (int i = 0; i < 8; ++i)
                #pragma unroll
                for (int j = 0; j < 8; ++j)
                    acc[i][j] += xf[i] * zf[j];
        }
        if (it + 1 < nIter) storeStage(buf ^ 1);
        __syncthreads();
    }

    float* dst = partial + (size_t)zs * M * N;
    #pragma unroll
    for (int i = 0; i < 8; ++i) {
        const int row = row0 + ty * 8 + i;
        if (row >= M) continue;
        #pragma unroll
        for (int j = 0; j < 8; ++j) {
            const int col = col0 + tx * 8 + j;
            if (col < N) dst[(size_t)row * N + col] = acc[i][j];
        }
    }
}

// ---------------- fused CG kernels (one block per RHS row) ----------------
__device__ __forceinline__ float blockReduce256(float v, float* sm)
{
    const int t = threadIdx.x;
    __syncthreads();
    sm[t] = v; __syncthreads();
    #pragma unroll
    for (int s = 128; s > 0; s >>= 1) {
        if (t < s) sm[t] += sm[t + s];
        __syncthreads();
    }
    return sm[0];
}

// init: reduce Cp partials -> C, set Y=0, Rr=Pd=C, rz=|C|^2
__global__ void cg_init(const float* __restrict__ Cp, float* __restrict__ C,
                        float* __restrict__ Y, float* __restrict__ Rr,
                        float* __restrict__ Pd, float* __restrict__ rz)
{
    __shared__ float sm[256];
    const int b = blockIdx.x, t = threadIdx.x;
    float s = 0.f;
    #pragma unroll
    for (int i = 0; i < 4; ++i) {
        const int j = t + i * 256;
        if (j < NANCH) {
            float c = 0.f;
            #pragma unroll
            for (int z = 0; z < CSPLIT_TC; ++z)
                c += Cp[(size_t)z * BPRIV * NANCH + b * NANCH + j];
            C[b * NANCH + j]  = c;
            Y[b * NANCH + j]  = 0.f;
            Rr[b * NANCH + j] = c;
            Pd[b * NANCH + j] = c;
            s += c * c;
        }
    }
    const float tot = blockReduce256(s, sm);
    if (t == 0) rz[b] = tot;
}

// one full CG step per block: reduce Vp, pv-dot, alpha, update Y/Rr, rz2, beta, next Pd
__global__ void cg_step(const float* __restrict__ Vp, float* __restrict__ Pd,
                        float* __restrict__ Y, float* __restrict__ Rr,
                        float* __restrict__ rz)
{
    __shared__ float sm[256];
    const int b = blockIdx.x, t = threadIdx.x;
    float v[4], p[4], rn[4];
    float dot = 0.f;
    #pragma unroll
    for (int i = 0; i < 4; ++i) {
        const int j = t + i * 256;
        float vv = 0.f, pp = 0.f;
        if (j < NANCH) {
            #pragma unroll
            for (int z = 0; z < VSPLIT; ++z)
                vv += Vp[(size_t)z * BPRIV * NANCH + b * NANCH + j];
            pp = Pd[b * NANCH + j];
        }
        v[i] = vv; p[i] = pp;
        dot += pp * vv;
    }
    const float pv = blockReduce256(dot, sm);
    const float rzb = rz[b];
    const float alpha = (pv > 0.f) ? rzb / pv : 0.f;

    float rs = 0.f;
    #pragma unroll
    for (int i = 0; i < 4; ++i) {
        const int j = t + i * 256;
        if (j < NANCH) {
            const float r = Rr[b * NANCH + j] - alpha * v[i];
            rn[i] = r;
            Y[b * NANCH + j] += alpha * p[i];
            rs += r * r;
        } else rn[i] = 0.f;
    }
    const float rz2 = blockReduce256(rs, sm);
    const float beta = (rzb > 0.f) ? rz2 / rzb : 0.f;
    #pragma unroll
    for (int i = 0; i < 4; ++i) {
        const int j = t + i * 256;
        if (j < NANCH) {
            Rr[b * NANCH + j] = rn[i];
            Pd[b * NANCH + j] = rn[i] + beta * p[i];
        }
    }
    if (t == 0) rz[b] = rz2;
}

// fused: scale_b = min(1/||emb_b||,1) with ||emb_b||^2 = <Y_b,C_b>, plus Y hi/lo split
__global__ void scaleSplit(const float* __restrict__ Y, const float* __restrict__ C,
                           float* __restrict__ scale,
                           __nv_bfloat16* __restrict__ Yh, __nv_bfloat16* __restrict__ Yl)
{
    __shared__ float sm[256];
    const int b = blockIdx.x, t = threadIdx.x;
    float s = 0.f;
    #pragma unroll
    for (int i = 0; i < 4; ++i) {
        const int j = t + i * 256;
        if (j < NANCH) {
            const float y = Y[b * NANCH + j];
            s += y * C[b * NANCH + j];
            const __nv_bfloat16 hb = __float2bfloat16(y);
            Yh[b * NANCH + j] = hb;
            Yl[b * NANCH + j] = __float2bfloat16(y - __bfloat162float(hb));
        }
    }
    const float tot = blockReduce256(s, sm);
    if (t == 0) {
        const float nrm = sqrtf(fmaxf(tot, 0.f));
        scale[b] = (nrm > 1.0f) ? 1.0f / nrm : 1.0f;
    }
}

// =====================================================================
extern "C" void kernel_launch(void* const* d_in, const int* in_sizes, int n_in,
                              void* d_out, int out_size)
{
    const float* A    = (const float*)d_in[0];   // pub_grad [1000, 100000]
    const float* priv = (const float*)d_in[1];   // priv_grad [256, 100000]
    float* out = (float*)d_out;                  // [256, 100000]

    __nv_bfloat16 *Ah, *Al, *Ath, *Atl, *Ph, *Pl, *Yh, *Yl;
    float *Gp, *G, *Cp, *C, *Y, *Rr, *Pd, *Vp, *rz, *sc;
    cudaGetSymbolAddress((void**)&Ah,  g_Ah);
    cudaGetSymbolAddress((void**)&Al,  g_Al);
    cudaGetSymbolAddress((void**)&Ath, g_Ath);
    cudaGetSymbolAddress((void**)&Atl, g_Atl);
    cudaGetSymbolAddress((void**)&Ph,  g_Ph);
    cudaGetSymbolAddress((void**)&Pl,  g_Pl);
    cudaGetSymbolAddress((void**)&Yh,  g_Yh);
    cudaGetSymbolAddress((void**)&Yl,  g_Yl);
    cudaGetSymbolAddress((void**)&Gp,  g_Gp);
    cudaGetSymbolAddress((void**)&G,   g_G);
    cudaGetSymbolAddress((void**)&Cp,  g_Cp);
    cudaGetSymbolAddress((void**)&C,   g_C);
    cudaGetSymbolAddress((void**)&Y,   g_Y);
    cudaGetSymbolAddress((void**)&Rr,  g_Rr);
    cudaGetSymbolAddress((void**)&Pd,  g_Pd);
    cudaGetSymbolAddress((void**)&Vp,  g_Vp);
    cudaGetSymbolAddress((void**)&rz,  g_rz);
    cudaGetSymbolAddress((void**)&sc,  g_scale);

    cudaFuncSetAttribute(mma_gemm_abt, cudaFuncAttributeMaxDynamicSharedMemorySize, MMA_SMEM);

    // 1) split A into bf16 hi/lo + transposed copies (R4 known-good path)
    convA<<<dim3(PDIM / 32, (NANCH + 31) / 32), dim3(32, 8)>>>(A, Ah, Al, Ath, Atl);
    // 2) split priv
    convSplit<<<960, 256>>>(priv, Ph, Pl, (size_t)BPRIV * PDIM);

    // 3) G = A A^T  (lower triangle; mirror fused into reduce)
    mma_gemm_abt<<<dim3(8, 8, GSPLIT_TC), 256, MMA_SMEM>>>(
        Ah, Al, Ah, Al, Gp, NANCH, NANCH, (size_t)PDIM, PDIM, GCHUNK, 1,
        0, nullptr, nullptr);
    reduceG<<<(NANCH * NANCH + 255) / 256, 256>>>(Gp, G);

    // 4) C = priv A^T  (partials reduced inside cg_init)
    mma_gemm_abt<<<dim3(8, 2, CSPLIT_TC), 256, MMA_SMEM>>>(
        Ph, Pl, Ah, Al, Cp, BPRIV, NANCH, (size_t)PDIM, PDIM, CCHUNK, 0,
        0, nullptr, nullptr);

    // 5) batched CG: G Y^T = C^T (256 RHS), fp32, fused steps
    cg_init<<<BPRIV, 256>>>(Cp, C, Y, Rr, Pd, rz);
    for (int it = 0; it < CG_ITERS; ++it) {
        gemm_abt_splitk<<<dim3(8, 2, VSPLIT), 256>>>(Pd, G, Vp, BPRIV, NANCH,
                                                     NANCH, NANCH, NANCH, 128);
        cg_step<<<BPRIV, 256>>>(Vp, Pd, Y, Rr, rz);
    }

    // 6) fused clip-scale + Y hi/lo split
    scaleSplit<<<BPRIV, 256>>>(Y, C, sc, Yh, Yl);

    // 7) W = Y * A with fused DP epilogue, direct to out (ABT via transposed A)
    mma_gemm_abt<<<dim3((PDIM + 127) / 128, 2, 1), 256, MMA_SMEM>>>(
        Yh, Yl, Ath, Atl, out, BPRIV, PDIM, (size_t)NANCH, NANCH, NANCH, 0,
        1, priv, sc);
}

// round 7
// speedup vs baseline: 1.2192x; 1.0165x over previous
#include <cuda_runtime.h>
#include <cuda_bf16.h>
#include <math.h>
#include <stdint.h>

// Problem constants (fixed by dataset)
#define PDIM  100000
#define NANCH 1000
#define BPRIV 256

constexpr int CG_ITERS  = 6;
constexpr int VSPLIT    = 8;      // fp32 CG matvec splits
constexpr int GSPLIT_TC = 4;      // split-K for G
constexpr int GCHUNK    = 25024;  // multiple of 64, 4*25024 >= 100000
constexpr int CSPLIT_TC = 9;      // split-K for C
constexpr int CCHUNK    = 11136;  // multiple of 64, 9*11136 >= 100000

// ---------------- static device scratch (no allocations allowed) ----------------
__device__ __align__(256) __nv_bfloat16 g_Ah [(size_t)NANCH * PDIM];   // 200 MB
__device__ __align__(256) __nv_bfloat16 g_Al [(size_t)NANCH * PDIM];   // 200 MB
__device__ __align__(256) __nv_bfloat16 g_Ath[(size_t)PDIM * NANCH];   // 200 MB
__device__ __align__(256) __nv_bfloat16 g_Atl[(size_t)PDIM * NANCH];   // 200 MB
__device__ __align__(256) __nv_bfloat16 g_Ph [(size_t)BPRIV * PDIM];   // 51 MB
__device__ __align__(256) __nv_bfloat16 g_Pl [(size_t)BPRIV * PDIM];   // 51 MB
__device__ __align__(256) __nv_bfloat16 g_Yh [BPRIV * NANCH];
__device__ __align__(256) __nv_bfloat16 g_Yl [BPRIV * NANCH];
__device__ float g_Gp[GSPLIT_TC * NANCH * NANCH];       // 16 MB
__device__ float g_G [NANCH * NANCH];
__device__ float g_Cp[CSPLIT_TC * BPRIV * NANCH];       // 9.2 MB
__device__ float g_C [BPRIV * NANCH];
__device__ float g_Y [BPRIV * NANCH];
__device__ float g_Rr[BPRIV * NANCH];
__device__ float g_Pd[BPRIV * NANCH];
__device__ float g_Vp[VSPLIT * BPRIV * NANCH];
__device__ float g_rz [BPRIV];
__device__ float g_scale[BPRIV];

// ---------------- PTX helpers (plain sm_103-compatible: sm_80+ features) ----------------
__device__ __forceinline__ uint32_t smem_u32(const void* p) {
    uint32_t a;
    asm("{ .reg .u64 t; cvta.to.shared.u64 t, %1; cvt.u32.u64 %0, t; }" : "=r"(a) : "l"(p));
    return a;
}
__device__ __forceinline__ void cp_async16(uint32_t dst, const void* src, int nbytes) {
    asm volatile("cp.async.cg.shared.global [%0], [%1], 16, %2;\n"
                 :: "r"(dst), "l"(src), "r"(nbytes) : "memory");
}
__device__ __forceinline__ void cp_commit() {
    asm volatile("cp.async.commit_group;" ::: "memory");
}
__device__ __forceinline__ void ldsm_x4(uint32_t* r, uint32_t addr) {
    asm volatile("ldmatrix.sync.aligned.m8n8.x4.shared.b16 {%0,%1,%2,%3}, [%4];"
                 : "=r"(r[0]), "=r"(r[1]), "=r"(r[2]), "=r"(r[3]) : "r"(addr));
}
__device__ __forceinline__ void ldsm_x2(uint32_t* r, uint32_t addr) {
    asm volatile("ldmatrix.sync.aligned.m8n8.x2.shared.b16 {%0,%1}, [%2];"
                 : "=r"(r[0]), "=r"(r[1]) : "r"(addr));
}
__device__ __forceinline__ void mma_bf16(float* d, const uint32_t* a, const uint32_t* b) {
    asm volatile("mma.sync.aligned.m16n8k16.row.col.f32.bf16.bf16.f32 "
                 "{%0,%1,%2,%3}, {%4,%5,%6,%7}, {%8,%9}, {%0,%1,%2,%3};"
                 : "+f"(d[0]), "+f"(d[1]), "+f"(d[2]), "+f"(d[3])
                 : "r"(a[0]), "r"(a[1]), "r"(a[2]), "r"(a[3]), "r"(b[0]), "r"(b[1]));
}

// =====================================================================
// Split-bf16 MMA GEMM:  partial[z] = X * Z^T
//   128x128 CTA tile, k-step 64, 8 warps (64x32 warp tiles, m16n8k16),
//   swizzled smem, 3-stage cp.async pipeline, 3 products hh+hl+lh.
//   R7: register-level fragment double-buffering across the 4 k16 sub-steps
//       (ldsm of ks+1 overlaps MMAs of ks); redundant trailing barrier removed.
//   Optional fused DP epilogue: out = scale[r]*w + clamp(priv-w, +-1e-3).
// =====================================================================
constexpr int TILE_B  = 128 * 128;         // one 128x64 bf16 tile = 16 KB
constexpr int STAGE_B = 4 * TILE_B;        // Xh,Xl,Zh,Zl = 64 KB
constexpr int NSTAGE  = 3;
constexpr int MMA_SMEM = NSTAGE * STAGE_B; // 192 KB

__global__ void __launch_bounds__(256, 1)
mma_gemm_abt(const __nv_bfloat16* __restrict__ Xh, const __nv_bfloat16* __restrict__ Xl,
             const __nv_bfloat16* __restrict__ Zh, const __nv_bfloat16* __restrict__ Zl,
             float* __restrict__ outp, int M, int N, size_t ldK,
             int kTotal, int kChunk, int lowerTri,
             int epi, const float* __restrict__ priv, const float* __restrict__ scale)
{
    if (lowerTri && blockIdx.x > blockIdx.y) return;
    extern __shared__ char smem[];
    const uint32_t sb = smem_u32(smem);
    const int tid = threadIdx.x, lane = tid & 31, wid = tid >> 5;
    const int wm = wid >> 2, wn = wid & 3;           // 2x4 warp grid
    const int row0 = blockIdx.y * 128, col0 = blockIdx.x * 128;
    const int kBeg = blockIdx.z * kChunk;
    int kEnd = kBeg + kChunk; if (kEnd > kTotal) kEnd = kTotal;
    const int nIter = (kEnd - kBeg + 63) >> 6;

    const __nv_bfloat16* bases[4] = {Xh, Xl, Zh, Zl};

    auto prefetch = [&](int s) {
        const int buf = s % NSTAGE;
        const int kb = kBeg + s * 64;
        #pragma unroll 4
        for (int i = 0; i < 16; ++i) {
            const int slot = i * 256 + tid;          // 0..4095
            const int t    = slot >> 10;             // tile 0..3
            const int w    = slot & 1023;
            const int row  = w >> 3;                 // 0..127
            const int ch   = w & 7;                  // 16B chunk
            const int rglob = ((t < 2) ? row0 : col0) + row;
            const int rmax  = (t < 2) ? M : N;
            const int kg = kb + ch * 8;
            int nb = 0;
            if (rglob < rmax) {
                int av = (kEnd - kg) * 2;
                nb = av < 0 ? 0 : (av > 16 ? 16 : av);
            }
            const __nv_bfloat16* src = (nb > 0) ? bases[t] + (size_t)rglob * ldK + kg
                                                : bases[t];
            const uint32_t dst = sb + (uint32_t)(buf * 4 + t) * (TILE_B)
                               + (uint32_t)(row << 7) + (uint32_t)((ch ^ (row & 7)) << 4);
            cp_async16(dst, src, nb);
        }
        cp_commit();
    };

    float acc[4][4][4];
    #pragma unroll
    for (int mt = 0; mt < 4; ++mt)
        #pragma unroll
        for (int nt = 0; nt < 4; ++nt)
            #pragma unroll
            for (int e = 0; e < 4; ++e) acc[mt][nt][e] = 0.f;

    prefetch(0);
    if (nIter > 1) prefetch(1);

    const int arow  = wm * 64 + (lane & 15);
    const int ahalf = lane >> 4;                    // k-half (0/1) within k16
    const int brow  = wn * 32 + (lane & 7);
    const int bhalf = (lane >> 3) & 1;

    // double-buffered register fragments
    uint32_t ah[2][4][4], al[2][4][4], bh[2][4][2], bl[2][4][2];

    for (int it = 0; it < nIter; ++it) {
        if (it + 1 < nIter) asm volatile("cp.async.wait_group 1;" ::: "memory");
        else                asm volatile("cp.async.wait_group 0;" ::: "memory");
        __syncthreads();   // also proves all warps finished reading stage (it-1)%3
        if (it + 2 < nIter) prefetch(it + 2);   // writes stage (it+2)%3 == (it-1)%3: safe

        const uint32_t tb  = sb + (uint32_t)(it % NSTAGE) * STAGE_B;
        const uint32_t tXh = tb, tXl = tb + TILE_B;
        const uint32_t tZh = tb + 2 * TILE_B, tZl = tb + 3 * TILE_B;

        auto loadFrag = [&](int ks, int fb) {
            #pragma unroll
            for (int mt = 0; mt < 4; ++mt) {
                const int r  = arow + mt * 16;
                const int ch = (ks * 2 + ahalf) ^ (r & 7);
                const uint32_t off = (uint32_t)(r << 7) + (uint32_t)(ch << 4);
                ldsm_x4(ah[fb][mt], tXh + off);
                ldsm_x4(al[fb][mt], tXl + off);
            }
            #pragma unroll
            for (int nt = 0; nt < 4; ++nt) {
                const int r  = brow + nt * 8;
                const int ch = (ks * 2 + bhalf) ^ (r & 7);
                const uint32_t off = (uint32_t)(r << 7) + (uint32_t)(ch << 4);
                ldsm_x2(bh[fb][nt], tZh + off);
                ldsm_x2(bl[fb][nt], tZl + off);
            }
        };

        loadFrag(0, 0);
        #pragma unroll
        for (int ks = 0; ks < 4; ++ks) {
            const int fb = ks & 1;
            if (ks < 3) loadFrag(ks + 1, fb ^ 1);   // overlap ldsm with MMAs below
            #pragma unroll
            for (int mt = 0; mt < 4; ++mt)
                #pragma unroll
                for (int nt = 0; nt < 4; ++nt) {
                    mma_bf16(acc[mt][nt], ah[fb][mt], bh[fb][nt]);
                    mma_bf16(acc[mt][nt], ah[fb][mt], bl[fb][nt]);
                    mma_bf16(acc[mt][nt], al[fb][mt], bh[fb][nt]);
                }
        }
        // no trailing __syncthreads: top-of-iter barrier provides the hazard fence
    }

    // store: d0,d1 -> (r, c..c+1); d2,d3 -> (r+8, c..c+1)
    float* dst = outp + (size_t)blockIdx.z * (size_t)M * N;
    #pragma unroll
    for (int mt = 0; mt < 4; ++mt) {
        const int rA = row0 + wm * 64 + mt * 16 + (lane >> 2);
        #pragma unroll
        for (int nt = 0; nt < 4; ++nt) {
            const int c = col0 + wn * 32 + nt * 8 + (lane & 3) * 2;
            #pragma unroll
            for (int h = 0; h < 2; ++h) {
                const int r = rA + h * 8;
                if (r >= M || c >= N) continue;
                const float v0 = acc[mt][nt][2 * h + 0];
                const float v1 = acc[mt][nt][2 * h + 1];
                float* po = dst + (size_t)r * N + c;
                if (epi) {
                    const float sc = scale[r];
                    const float* pp = priv + (size_t)r * N + c;
                    float r0 = pp[0] - v0; r0 = fminf(fmaxf(r0, -1e-3f), 1e-3f);
                    float r1 = pp[1] - v1; r1 = fminf(fmaxf(r1, -1e-3f), 1e-3f);
                    *(float2*)po = make_float2(sc * v0 + r0, sc * v1 + r1);
                } else {
                    *(float2*)po = make_float2(v0, v1);
                }
            }
        }
    }
}

// ---------------- converts ----------------
__global__ void convA(const float* __restrict__ A,
                      __nv_bfloat16* __restrict__ Ah, __nv_bfloat16* __restrict__ Al,
                      __nv_bfloat16* __restrict__ Ath, __nv_bfloat16* __restrict__ Atl)
{
    __shared__ __nv_bfloat16 sh[32][33];
    __shared__ __nv_bfloat16 sl[32][33];
    const int tx = threadIdx.x, ty = threadIdx.y;
    const int col = blockIdx.x * 32 + tx;      // p
    #pragma unroll
    for (int k = 0; k < 4; ++k) {
        const int row = blockIdx.y * 32 + ty + k * 8;   // n
        float v = 0.f;
        if (row < NANCH) v = A[(size_t)row * PDIM + col];
        const __nv_bfloat16 hb = __float2bfloat16(v);
        const __nv_bfloat16 lb = __float2bfloat16(v - __bfloat162float(hb));
        if (row < NANCH) {
            Ah[(size_t)row * PDIM + col] = hb;
            Al[(size_t)row * PDIM + col] = lb;
        }
        sh[ty + k * 8][tx] = hb;
        sl[ty + k * 8][tx] = lb;
    }
    __syncthreads();
    #pragma unroll
    for (int k = 0; k < 4; ++k) {
        const int p = blockIdx.x * 32 + ty + k * 8;
        const int n = blockIdx.y * 32 + tx;
        if (n < NANCH) {
            Ath[(size_t)p * NANCH + n] = sh[tx][ty + k * 8];
            Atl[(size_t)p * NANCH + n] = sl[tx][ty + k * 8];
        }
    }
}

__global__ void convSplit(const float* __restrict__ X,
                          __nv_bfloat16* __restrict__ H, __nv_bfloat16* __restrict__ L,
                          size_t n)
{
    const size_t i = ((size_t)blockIdx.x * blockDim.x + threadIdx.x) * 2;
    const size_t stride = (size_t)gridDim.x * blockDim.x * 2;
    for (size_t j = i; j < n; j += stride) {
        if (j + 2 <= n) {
            const float2 v = *(const float2*)(X + j);
            const __nv_bfloat16 h0 = __float2bfloat16(v.x);
            const __nv_bfloat16 h1 = __float2bfloat16(v.y);
            __nv_bfloat162 hh; hh.x = h0; hh.y = h1;
            __nv_bfloat162 ll;
            ll.x = __float2bfloat16(v.x - __bfloat162float(h0));
            ll.y = __float2bfloat16(v.y - __bfloat162float(h1));
            *(__nv_bfloat162*)(H + j) = hh;
            *(__nv_bfloat162*)(L + j) = ll;
        } else {
            const float v = X[j];
            const __nv_bfloat16 hb = __float2bfloat16(v);
            H[j] = hb;
            L[j] = __float2bfloat16(v - __bfloat162float(hb));
        }
    }
}

// ---------------- G reduce + mirror (lower-tri partials, fused) ----------------
__global__ void reduceG(const float* __restrict__ Gp, float* __restrict__ G)
{
    const int idx = blockIdx.x * 256 + threadIdx.x;
    if (idx >= NANCH * NANCH) return;
    const int i = idx / NANCH, j = idx - i * NANCH;
    const int s0 = (j > i) ? (j * NANCH + i) : idx;
    float s = 0.f;
    #pragma unroll
    for (int z = 0; z < GSPLIT_TC; ++z) s += Gp[(size_t)z * NANCH * NANCH + s0];
    G[idx] = s;
}

// =====================================================================
// fp32 SIMT split-K GEMM (CG matvec only: Pd[256x1000] @ G[1000x1000])
// =====================================================================
__global__ void __launch_bounds__(256, 2)
gemm_abt_splitk(const float* __restrict__ X, const float* __restrict__ Z,
                float* __restrict__ partial,
                int M, int N, int ldx, int ldz, int kTotal, int kChunk)
{
    __shared__ __align__(16) float Xs[2][16][132];
    __shared__ __align__(16) float Zs[2][16][132];

    const int tid = threadIdx.x;
    const int bj = blockIdx.x, bi = blockIdx.y, zs = blockIdx.z;
    const int row0 = bi * 128, col0 = bj * 128;
    const int kBeg = zs * kChunk;
    int kEnd = kBeg + kChunk; if (kEnd > kTotal) kEnd = kTotal;
    const int nIter = (kEnd - kBeg + 15) >> 4;

    const int rbase = tid >> 2;
    const int c0    = (tid & 3) << 2;
    const int tx = tid & 15, ty = tid >> 4;

    float4 sx[2], sz[2];

    auto loadStage = [&](int it) {
        const int kb = kBeg + it * 16;
        const int k  = kb + c0;
        #pragma unroll
        for (int q = 0; q < 2; ++q) {
            const int rr = rbase + q * 64;
            float4 v = make_float4(0.f, 0.f, 0.f, 0.f);
            const int row = row0 + rr;
            if (row < M) {
                const float* p = X + (size_t)row * ldx + k;
                if (k + 4 <= kEnd) v = *(const float4*)p;
                else { float* pv = (float*)&v; for (int e = 0; e < 4; ++e) if (k + e < kEnd) pv[e] = p[e]; }
            }
            sx[q] = v;
            float4 w = make_float4(0.f, 0.f, 0.f, 0.f);
            const int colr = col0 + rr;
            if (colr < N) {
                const float* p = Z + (size_t)colr * ldz + k;
                if (k + 4 <= kEnd) w = *(const float4*)p;
                else { float* pw = (float*)&w; for (int e = 0; e < 4; ++e) if (k + e < kEnd) pw[e] = p[e]; }
            }
            sz[q] = w;
        }
    };
    auto storeStage = [&](int buf) {
        #pragma unroll
        for (int q = 0; q < 2; ++q) {
            const int rr = rbase + q * 64;
            Xs[buf][c0+0][rr] = sx[q].x; Xs[buf][c0+1][rr] = sx[q].y;
            Xs[buf][c0+2][rr] = sx[q].z; Xs[buf][c0+3][rr] = sx[q].w;
            Zs[buf][c0+0][rr] = sz[q].x; Zs[buf][c0+1][rr] = sz[q].y;
            Zs[buf][c0+2][rr] = sz[q].z; Zs[buf][c0+3][rr] = sz[q].w;
        }
    };

    float acc[8][8];
    #pragma unroll
    for (int i = 0; i < 8; ++i)
        #pragma unroll
        for (int j = 0; j < 8; ++j) acc[i][j] = 0.f;

    loadStage(0); storeStage(0); __syncthreads();

    for (int it = 0; it < nIter; ++it) {
        const int buf = it & 1;
        if (it + 1 < nIter) loadStage(it + 1);
        #pragma unroll
        for (int k = 0; k < 16; ++k) {
            float xf[8], zf[8];
            *(float4*)(xf)     = *(const float4*)&Xs[buf][k][ty*8];
            *(float4*)(xf + 4) = *(const float4*)&Xs[buf][k][ty*8 + 4];
            *(float4*)(zf)     = *(const float4*)&Zs[buf][k][tx*8];
            *(float4*)(zf + 4) = *(const float4*)&Zs[buf][k][tx*8 + 4];
            #pragma unroll
            for (int i = 0; i < 8; ++i)
                #pragma unroll
                for (int j = 0; j < 8; ++j)
                    acc[i][j] += xf[i] * zf[j];
        }
        if (it + 1 < nIter) storeStage(buf ^ 1);
        __syncthreads();
    }

    float* dst = partial + (size_t)zs * M * N;
    #pragma unroll
    for (int i = 0; i < 8; ++i) {
        const int row = row0 + ty * 8 + i;
        if (row >= M) continue;
        #pragma unroll
        for (int j = 0; j < 8; ++j) {
            const int col = col0 + tx * 8 + j;
            if (col < N) dst[(size_t)row * N + col] = acc[i][j];
        }
    }
}

// ---------------- fused CG kernels (one block per RHS row) ----------------
__device__ __forceinline__ float blockReduce256(float v, float* sm)
{
    const int t = threadIdx.x;
    __syncthreads();
    sm[t] = v; __syncthreads();
    #pragma unroll
    for (int s = 128; s > 0; s >>= 1) {
        if (t < s) sm[t] += sm[t + s];
        __syncthreads();
    }
    return sm[0];
}

// init: reduce Cp partials -> C, set Y=0, Rr=Pd=C, rz=|C|^2
__global__ void cg_init(const float* __restrict__ Cp, float* __restrict__ C,
                        float* __restrict__ Y, float* __restrict__ Rr,
                        float* __restrict__ Pd, float* __restrict__ rz)
{
    __shared__ float sm[256];
    const int b = blockIdx.x, t = threadIdx.x;
    float s = 0.f;
    #pragma unroll
    for (int i = 0; i < 4; ++i) {
        const int j = t + i * 256;
        if (j < NANCH) {
            float c = 0.f;
            #pragma unroll
            for (int z = 0; z < CSPLIT_TC; ++z)
                c += Cp[(size_t)z * BPRIV * NANCH + b * NANCH + j];
            C[b * NANCH + j]  = c;
            Y[b * NANCH + j]  = 0.f;
            Rr[b * NANCH + j] = c;
            Pd[b * NANCH + j] = c;
            s += c * c;
        }
    }
    const float tot = blockReduce256(s, sm);
    if (t == 0) rz[b] = tot;
}

// one full CG step per block: reduce Vp, pv-dot, alpha, update Y/Rr, rz2, beta, next Pd
__global__ void cg_step(const float* __restrict__ Vp, float* __restrict__ Pd,
                        float* __restrict__ Y, float* __restrict__ Rr,
                        float* __restrict__ rz)
{
    __shared__ float sm[256];
    const int b = blockIdx.x, t = threadIdx.x;
    float v[4], p[4], rn[4];
    float dot = 0.f;
    #pragma unroll
    for (int i = 0; i < 4; ++i) {
        const int j = t + i * 256;
        float vv = 0.f, pp = 0.f;
        if (j < NANCH) {
            #pragma unroll
            for (int z = 0; z < VSPLIT; ++z)
                vv += Vp[(size_t)z * BPRIV * NANCH + b * NANCH + j];
            pp = Pd[b * NANCH + j];
        }
        v[i] = vv; p[i] = pp;
        dot += pp * vv;
    }
    const float pv = blockReduce256(dot, sm);
    const float rzb = rz[b];
    const float alpha = (pv > 0.f) ? rzb / pv : 0.f;

    float rs = 0.f;
    #pragma unroll
    for (int i = 0; i < 4; ++i) {
        const int j = t + i * 256;
        if (j < NANCH) {
            const float r = Rr[b * NANCH + j] - alpha * v[i];
            rn[i] = r;
            Y[b * NANCH + j] += alpha * p[i];
            rs += r * r;
        } else rn[i] = 0.f;
    }
    const float rz2 = blockReduce256(rs, sm);
    const float beta = (rzb > 0.f) ? rz2 / rzb : 0.f;
    #pragma unroll
    for (int i = 0; i < 4; ++i) {
        const int j = t + i * 256;
        if (j < NANCH) {
            Rr[b * NANCH + j] = rn[i];
            Pd[b * NANCH + j] = rn[i] + beta * p[i];
        }
    }
    if (t == 0) rz[b] = rz2;
}

// fused: scale_b = min(1/||emb_b||,1) with ||emb_b||^2 = <Y_b,C_b>, plus Y hi/lo split
__global__ void scaleSplit(const float* __restrict__ Y, const float* __restrict__ C,
                           float* __restrict__ scale,
                           __nv_bfloat16* __restrict__ Yh, __nv_bfloat16* __restrict__ Yl)
{
    __shared__ float sm[256];
    const int b = blockIdx.x, t = threadIdx.x;
    float s = 0.f;
    #pragma unroll
    for (int i = 0; i < 4; ++i) {
        const int j = t + i * 256;
        if (j < NANCH) {
            const float y = Y[b * NANCH + j];
            s += y * C[b * NANCH + j];
            const __nv_bfloat16 hb = __float2bfloat16(y);
            Yh[b * NANCH + j] = hb;
            Yl[b * NANCH + j] = __float2bfloat16(y - __bfloat162float(hb));
        }
    }
    const float tot = blockReduce256(s, sm);
    if (t == 0) {
        const float nrm = sqrtf(fmaxf(tot, 0.f));
        scale[b] = (nrm > 1.0f) ? 1.0f / nrm : 1.0f;
    }
}

// =====================================================================
extern "C" void kernel_launch(void* const* d_in, const int* in_sizes, int n_in,
                              void* d_out, int out_size)
{
    const float* A    = (const float*)d_in[0];   // pub_grad [1000, 100000]
    const float* priv = (const float*)d_in[1];   // priv_grad [256, 100000]
    float* out = (float*)d_out;                  // [256, 100000]

    __nv_bfloat16 *Ah, *Al, *Ath, *Atl, *Ph, *Pl, *Yh, *Yl;
    float *Gp, *G, *Cp, *C, *Y, *Rr, *Pd, *Vp, *rz, *sc;
    cudaGetSymbolAddress((void**)&Ah,  g_Ah);
    cudaGetSymbolAddress((void**)&Al,  g_Al);
    cudaGetSymbolAddress((void**)&Ath, g_Ath);
    cudaGetSymbolAddress((void**)&Atl, g_Atl);
    cudaGetSymbolAddress((void**)&Ph,  g_Ph);
    cudaGetSymbolAddress((void**)&Pl,  g_Pl);
    cudaGetSymbolAddress((void**)&Yh,  g_Yh);
    cudaGetSymbolAddress((void**)&Yl,  g_Yl);
    cudaGetSymbolAddress((void**)&Gp,  g_Gp);
    cudaGetSymbolAddress((void**)&G,   g_G);
    cudaGetSymbolAddress((void**)&Cp,  g_Cp);
    cudaGetSymbolAddress((void**)&C,   g_C);
    cudaGetSymbolAddress((void**)&Y,   g_Y);
    cudaGetSymbolAddress((void**)&Rr,  g_Rr);
    cudaGetSymbolAddress((void**)&Pd,  g_Pd);
    cudaGetSymbolAddress((void**)&Vp,  g_Vp);
    cudaGetSymbolAddress((void**)&rz,  g_rz);
    cudaGetSymbolAddress((void**)&sc,  g_scale);

    cudaFuncSetAttribute(mma_gemm_abt, cudaFuncAttributeMaxDynamicSharedMemorySize, MMA_SMEM);

    // 1) split A into bf16 hi/lo + transposed copies
    convA<<<dim3(PDIM / 32, (NANCH + 31) / 32), dim3(32, 8)>>>(A, Ah, Al, Ath, Atl);
    // 2) split priv
    convSplit<<<960, 256>>>(priv, Ph, Pl, (size_t)BPRIV * PDIM);

    // 3) G = A A^T  (lower triangle; mirror fused into reduce)
    mma_gemm_abt<<<dim3(8, 8, GSPLIT_TC), 256, MMA_SMEM>>>(
        Ah, Al, Ah, Al, Gp, NANCH, NANCH, (size_t)PDIM, PDIM, GCHUNK, 1,
        0, nullptr, nullptr);
    reduceG<<<(NANCH * NANCH + 255) / 256, 256>>>(Gp, G);

    // 4) C = priv A^T  (partials reduced inside cg_init)
    mma_gemm_abt<<<dim3(8, 2, CSPLIT_TC), 256, MMA_SMEM>>>(
        Ph, Pl, Ah, Al, Cp, BPRIV, NANCH, (size_t)PDIM, PDIM, CCHUNK, 0,
        0, nullptr, nullptr);

    // 5) batched CG: G Y^T = C^T (256 RHS), fp32, fused steps
    cg_init<<<BPRIV, 256>>>(Cp, C, Y, Rr, Pd, rz);
    for (int it = 0; it < CG_ITERS; ++it) {
        gemm_abt_splitk<<<dim3(8, 2, VSPLIT), 256>>>(Pd, G, Vp, BPRIV, NANCH,
                                                     NANCH, NANCH, NANCH, 128);
        cg_step<<<BPRIV, 256>>>(Vp, Pd, Y, Rr, rz);
    }

    // 6) fused clip-scale + Y hi/lo split
    scaleSplit<<<BPRIV, 256>>>(Y, C, sc, Yh, Yl);

    // 7) W = Y * A with fused DP epilogue, direct to out (ABT via transposed A)
    mma_gemm_abt<<<dim3((PDIM + 127) / 128, 2, 1), 256, MMA_SMEM>>>(
        Yh, Yl, Ath, Atl, out, BPRIV, PDIM, (size_t)NANCH, NANCH, NANCH, 0,
        1, priv, sc);
}